// round 12
// baseline (speedup 1.0000x reference)
#include <cuda_runtime.h>
#include <cuda_fp16.h>
#include <cstdint>
#include <math.h>

#define H_DIM 1024
#define F_DIM 4096
#define N_EXP 8
#define MAX_T 4096
#define MAX_A (MAX_T * 2)

#define BM 128
#define BN 128
#define BK 32
#define TS 40                     // A smem stride (halves): 80 B, conflict-free
#define BS 136                    // B fp16 smem stride (halves): 272 B
#define A_TILE_B (BM * TS * 2)    // 10240 B
#define B_TILE_B (BK * BS * 2)    // 8704 B fp16 tile (one matrix)
#define NT 512                    // GEMM CTA threads (16 warps)

// rings: A x3, fp32 staging x3, fp16 x2
#define GU_STG   32768                       // 2 matrices x 32x128 fp32
#define GU_A3    (3 * A_TILE_B)              // 30720
#define GU_HBASE (GU_A3 + 3 * GU_STG)        // 129024
#define GU_SMEM  (GU_HBASE + 2 * 2 * B_TILE_B)  // 163840
#define DN_STG   16384
#define DN_A3    (3 * A_TILE_B)
#define DN_HBASE (DN_A3 + 3 * DN_STG)        // 79872
#define DN_SMEM  (DN_HBASE + 2 * B_TILE_B)   // 97280

// ---------------------------------------------------------------------------
// Scratch (__device__ globals; referenced ONLY inside device code)
// ---------------------------------------------------------------------------
__device__ __half g_x16[(size_t)MAX_A * H_DIM];   // gathered x rows, fp16
__device__ __half g_h16[(size_t)MAX_A * F_DIM];   // silu(g)*u, fp16
__device__ float  g_y[(size_t)MAX_A * H_DIM];     // down output, fp32
__device__ int    g_counts[N_EXP];
__device__ int    g_offsets[N_EXP + 1];
__device__ int    g_cursor[N_EXP];
__device__ int    g_tok[MAX_A];
__device__ int    g_pos[MAX_A];
__device__ int    g_topE[MAX_A];
__device__ float  g_topW[MAX_A];

// ---------------------------------------------------------------------------
// helpers
// ---------------------------------------------------------------------------
__device__ __forceinline__ uint32_t smem_u32(const void* p) {
    uint32_t a;
    asm("{ .reg .u64 t; cvta.to.shared.u64 t, %1; cvt.u32.u64 %0, t; }" : "=r"(a) : "l"(p));
    return a;
}
__device__ __forceinline__ void cpa16(uint32_t s, const void* g) {
    asm volatile("cp.async.cg.shared.global [%0], [%1], 16;" :: "r"(s), "l"(g));
}
__device__ __forceinline__ void cpa_commit() { asm volatile("cp.async.commit_group;" ::: "memory"); }
template <int N> __device__ __forceinline__ void cpa_wait() {
    asm volatile("cp.async.wait_group %0;" :: "n"(N) : "memory");
}
__device__ __forceinline__ void mma16(float* c, const uint32_t* a, const uint32_t* b) {
    asm volatile(
        "mma.sync.aligned.m16n8k16.row.col.f32.f16.f16.f32 "
        "{%0,%1,%2,%3}, {%4,%5,%6,%7}, {%8,%9}, {%0,%1,%2,%3};"
        : "+f"(c[0]), "+f"(c[1]), "+f"(c[2]), "+f"(c[3])
        : "r"(a[0]), "r"(a[1]), "r"(a[2]), "r"(a[3]), "r"(b[0]), "r"(b[1]));
}
__device__ __forceinline__ void ldm_x4(uint32_t* r, uint32_t a) {
    asm volatile("ldmatrix.sync.aligned.m8n8.x4.shared.b16 {%0,%1,%2,%3}, [%4];"
        : "=r"(r[0]), "=r"(r[1]), "=r"(r[2]), "=r"(r[3]) : "r"(a));
}
__device__ __forceinline__ void ldm_x4_t(uint32_t* r, uint32_t a) {
    asm volatile("ldmatrix.sync.aligned.m8n8.x4.trans.shared.b16 {%0,%1,%2,%3}, [%4];"
        : "=r"(r[0]), "=r"(r[1]), "=r"(r[2]), "=r"(r[3]) : "r"(a));
}
__device__ __forceinline__ void cvt_store8(char* dst, float4 v) {
    __half2 h0 = __floats2half2_rn(v.x, v.y);
    __half2 h1 = __floats2half2_rn(v.z, v.w);
    uint2 u;
    u.x = *(const uint32_t*)&h0;
    u.y = *(const uint32_t*)&h1;
    *(uint2*)dst = u;
}

// ---------------------------------------------------------------------------
// Routing
// ---------------------------------------------------------------------------
__global__ void zero_kernel() {
    if (threadIdx.x < N_EXP) g_counts[threadIdx.x] = 0;
}

__global__ void router_kernel(const float* __restrict__ x,
                              const float* __restrict__ wg, int T) {
    int warp = (blockIdx.x * blockDim.x + threadIdx.x) >> 5;
    int lane = threadIdx.x & 31;
    if (warp >= T) return;
    const float* xr = x + (size_t)warp * H_DIM;

    float acc[N_EXP];
#pragma unroll
    for (int e = 0; e < N_EXP; e++) acc[e] = 0.0f;
    for (int k = lane; k < H_DIM; k += 32) {
        float xv = xr[k];
        const float* w = wg + (size_t)k * N_EXP;
#pragma unroll
        for (int e = 0; e < N_EXP; e++) acc[e] += xv * w[e];
    }
#pragma unroll
    for (int e = 0; e < N_EXP; e++)
#pragma unroll
        for (int o = 16; o > 0; o >>= 1)
            acc[e] += __shfl_xor_sync(0xFFFFFFFFu, acc[e], o);

    if (lane == 0) {
        float mx = acc[0];
#pragma unroll
        for (int e = 1; e < N_EXP; e++) mx = fmaxf(mx, acc[e]);
        float p[N_EXP], s = 0.0f;
#pragma unroll
        for (int e = 0; e < N_EXP; e++) { p[e] = __expf(acc[e] - mx); s += p[e]; }
        float inv = 1.0f / s;
        int e0 = 0;
#pragma unroll
        for (int e = 1; e < N_EXP; e++) if (p[e] > p[e0]) e0 = e;
        int e1 = (e0 == 0) ? 1 : 0;
#pragma unroll
        for (int e = 0; e < N_EXP; e++) if (e != e0 && p[e] > p[e1]) e1 = e;
        g_topE[warp * 2 + 0] = e0; g_topW[warp * 2 + 0] = p[e0] * inv;
        g_topE[warp * 2 + 1] = e1; g_topW[warp * 2 + 1] = p[e1] * inv;
        atomicAdd(&g_counts[e0], 1);
        atomicAdd(&g_counts[e1], 1);
    }
}

__global__ void offsets_kernel() {
    int s = 0;
    g_offsets[0] = 0;
#pragma unroll
    for (int e = 0; e < N_EXP; e++) {
        g_cursor[e] = s;
        s += g_counts[e];
        g_offsets[e + 1] = s;
    }
}

__global__ void scatter_kernel(int T) {
    int i = blockIdx.x * blockDim.x + threadIdx.x;
    if (i >= 2 * T) return;
    int e = g_topE[i];
    int pos = atomicAdd(&g_cursor[e], 1);
    g_tok[pos] = i >> 1;
    g_pos[i] = pos;
}

// Gather x rows into contiguous fp16 buffer.
__global__ void gather_kernel(const float* __restrict__ x) {
    int a = blockIdx.x;
    int tok = g_tok[a];
    const float4* src = (const float4*)(x + (size_t)tok * H_DIM);
    float4 v = src[threadIdx.x];
    __half2* dst = (__half2*)(g_x16 + (size_t)a * H_DIM) + threadIdx.x * 2;
    dst[0] = __floats2half2_rn(v.x, v.y);
    dst[1] = __floats2half2_rn(v.z, v.w);
}

// ---------------------------------------------------------------------------
// Fused gate+up GEMM, fp32 weights converted in-kernel:
// h = silu(Xg@Wg) * (Xg@Wu); 128x128 CTA tile, 16 warps, 32x32 warp tiles.
// ---------------------------------------------------------------------------
__global__ __launch_bounds__(NT)
void gateup_kernel(const float* __restrict__ Wg, const float* __restrict__ Wu) {
    constexpr int K = H_DIM, N = F_DIM, NCH = K / BK;   // 32 chunks

    int e = blockIdx.z;
    int beg = g_offsets[e], end = g_offsets[e + 1];
    int m0 = beg + (int)blockIdx.y * BM;
    if (m0 >= end) return;
    int n0 = blockIdx.x * BN;

    const float* Bg = Wg + (size_t)e * K * N + n0;
    const float* Bu = Wu + (size_t)e * K * N + n0;

    extern __shared__ char smem[];
    uint32_t sb = smem_u32(smem);

    int tid = threadIdx.x;
    int wid = tid >> 5, lane = tid & 31;
    int wm = (wid & 3) * 32;
    int wn = (wid >> 2) * 32;
    int gr = lane >> 2, qc = (lane & 3) * 2;

    int a_row = (lane & 15), a_koff = (lane >> 4) << 3;
    int b_krow = (lane & 7) + (((lane >> 3) & 1) << 3);
    int b_noff = (lane >> 4) << 3;

    auto load_chunk = [&](int c) {
        int k0 = c * BK;
        uint32_t aB = sb + (uint32_t)(c % 3) * A_TILE_B;
        {
            int row = tid >> 2, q = tid & 3;
            int r = m0 + row; if (r >= end) r = end - 1;
            cpa16(aB + (uint32_t)(row * (TS * 2) + q * 16),
                  g_x16 + (size_t)r * K + k0 + q * 8);
        }
        uint32_t sB = sb + GU_A3 + (uint32_t)(c % 3) * GU_STG;
#pragma unroll
        for (int j = 0; j < 2; j++) {
            int idx = tid + j * 512;
            int kr = idx >> 5, qq = idx & 31;
            uint32_t so = (uint32_t)(kr * 512 + qq * 16);
            size_t go = (size_t)(k0 + kr) * N + qq * 4;
            cpa16(sB + so, Bg + go);
            cpa16(sB + 16384 + so, Bu + go);
        }
        cpa_commit();
    };

    // Each thread converts exactly the fp32 bytes IT cp.async'd (no sync needed).
    auto convert = [&](int c) {
        const char* sB = smem + GU_A3 + (size_t)(c % 3) * GU_STG;
        char* hB = smem + GU_HBASE + (size_t)(c % 2) * (2 * B_TILE_B);
#pragma unroll
        for (int j = 0; j < 2; j++) {
            int idx = tid + j * 512;
            int kr = idx >> 5, qq = idx & 31;
            int soff = kr * 512 + qq * 16;
            int hoff = kr * (BS * 2) + qq * 8;
            cvt_store8(hB + hoff,             *(const float4*)(sB + soff));
            cvt_store8(hB + B_TILE_B + hoff,  *(const float4*)(sB + 16384 + soff));
        }
    };

    float accg[2][4][4], accu[2][4][4];
#pragma unroll
    for (int mf = 0; mf < 2; mf++)
#pragma unroll
        for (int nf = 0; nf < 4; nf++)
#pragma unroll
            for (int i = 0; i < 4; i++) { accg[mf][nf][i] = 0.0f; accu[mf][nf][i] = 0.0f; }

    load_chunk(0);
    load_chunk(1);
    cpa_wait<1>();            // group 0 complete (own-thread)
    convert(0);
    __syncthreads();          // publish fp16 slot 0 + A slot 0

    for (int c = 0; c < NCH; c++) {
        if (c + 2 < NCH) load_chunk(c + 2);
        if (c + 1 < NCH) {
            if (c + 2 < NCH) cpa_wait<1>(); else cpa_wait<0>();
            convert(c + 1);
        }

        uint32_t stA  = sb + (uint32_t)(c % 3) * A_TILE_B;
        uint32_t stBg = sb + GU_HBASE + (uint32_t)(c % 2) * (2 * B_TILE_B);
        uint32_t stBu = stBg + B_TILE_B;

#pragma unroll
        for (int ks = 0; ks < 2; ks++) {
            int kb = ks * 16;
            uint32_t a[2][4];
#pragma unroll
            for (int mf = 0; mf < 2; mf++)
                ldm_x4(a[mf], stA + (uint32_t)(((wm + mf * 16 + a_row) * TS + kb + a_koff) * 2));

            int bk = kb + b_krow;
#pragma unroll
            for (int pf = 0; pf < 2; pf++) {
                int bn = wn + pf * 16 + b_noff;
                uint32_t bg[4], bu[4];
                ldm_x4_t(bg, stBg + (uint32_t)((bk * BS + bn) * 2));
                ldm_x4_t(bu, stBu + (uint32_t)((bk * BS + bn) * 2));
#pragma unroll
                for (int sub = 0; sub < 2; sub++) {
                    int nf = pf * 2 + sub;
#pragma unroll
                    for (int mf = 0; mf < 2; mf++) {
                        mma16(accg[mf][nf], a[mf], bg + sub * 2);
                        mma16(accu[mf][nf], a[mf], bu + sub * 2);
                    }
                }
            }
        }
        __syncthreads();   // fp16 slot c reads done before overwrite; slot c+1 published
    }

    // epilogue: h = silu(g) * u, fp16
#pragma unroll
    for (int mf = 0; mf < 2; mf++) {
#pragma unroll
        for (int nf = 0; nf < 4; nf++) {
            int row0 = m0 + wm + mf * 16 + gr;
            int col  = n0 + wn + nf * 8 + qc;
            if (row0 < end) {
                float gv0 = accg[mf][nf][0], gv1 = accg[mf][nf][1];
                float h0 = (gv0 / (1.0f + __expf(-gv0))) * accu[mf][nf][0];
                float h1 = (gv1 / (1.0f + __expf(-gv1))) * accu[mf][nf][1];
                *(__half2*)(g_h16 + (size_t)row0 * F_DIM + col) = __floats2half2_rn(h0, h1);
            }
            int row1 = row0 + 8;
            if (row1 < end) {
                float gv2 = accg[mf][nf][2], gv3 = accg[mf][nf][3];
                float h2 = (gv2 / (1.0f + __expf(-gv2))) * accu[mf][nf][2];
                float h3 = (gv3 / (1.0f + __expf(-gv3))) * accu[mf][nf][3];
                *(__half2*)(g_h16 + (size_t)row1 * F_DIM + col) = __floats2half2_rn(h2, h3);
            }
        }
    }
}

// ---------------------------------------------------------------------------
// Down GEMM, fp32 weights converted in-kernel: y = h @ Wd (K=4096, N=1024)
// ---------------------------------------------------------------------------
__global__ __launch_bounds__(NT)
void down_kernel(const float* __restrict__ Wd) {
    constexpr int K = F_DIM, N = H_DIM, NCH = K / BK;   // 128 chunks

    int e = blockIdx.z;
    int beg = g_offsets[e], end = g_offsets[e + 1];
    int m0 = beg + (int)blockIdx.y * BM;
    if (m0 >= end) return;
    int n0 = blockIdx.x * BN;

    const float* Bm = Wd + (size_t)e * K * N + n0;

    extern __shared__ char smem[];
    uint32_t sb = smem_u32(smem);

    int tid = threadIdx.x;
    int wid = tid >> 5, lane = tid & 31;
    int wm = (wid & 3) * 32;
    int wn = (wid >> 2) * 32;
    int gr = lane >> 2, qc = (lane & 3) * 2;

    int a_row = (lane & 15), a_koff = (lane >> 4) << 3;
    int b_krow = (lane & 7) + (((lane >> 3) & 1) << 3);
    int b_noff = (lane >> 4) << 3;

    auto load_chunk = [&](int c) {
        int k0 = c * BK;
        uint32_t aB = sb + (uint32_t)(c % 3) * A_TILE_B;
        {
            int row = tid >> 2, q = tid & 3;
            int r = m0 + row; if (r >= end) r = end - 1;
            cpa16(aB + (uint32_t)(row * (TS * 2) + q * 16),
                  g_h16 + (size_t)r * K + k0 + q * 8);
        }
        uint32_t sB = sb + DN_A3 + (uint32_t)(c % 3) * DN_STG;
#pragma unroll
        for (int j = 0; j < 2; j++) {
            int idx = tid + j * 512;
            int kr = idx >> 5, qq = idx & 31;
            cpa16(sB + (uint32_t)(kr * 512 + qq * 16),
                  Bm + (size_t)(k0 + kr) * N + qq * 4);
        }
        cpa_commit();
    };

    auto convert = [&](int c) {
        const char* sB = smem + DN_A3 + (size_t)(c % 3) * DN_STG;
        char* hB = smem + DN_HBASE + (size_t)(c % 2) * B_TILE_B;
#pragma unroll
        for (int j = 0; j < 2; j++) {
            int idx = tid + j * 512;
            int kr = idx >> 5, qq = idx & 31;
            cvt_store8(hB + kr * (BS * 2) + qq * 8,
                       *(const float4*)(sB + kr * 512 + qq * 16));
        }
    };

    float acc[2][4][4];
#pragma unroll
    for (int mf = 0; mf < 2; mf++)
#pragma unroll
        for (int nf = 0; nf < 4; nf++)
#pragma unroll
            for (int i = 0; i < 4; i++) acc[mf][nf][i] = 0.0f;

    load_chunk(0);
    load_chunk(1);
    cpa_wait<1>();
    convert(0);
    __syncthreads();

    for (int c = 0; c < NCH; c++) {
        if (c + 2 < NCH) load_chunk(c + 2);
        if (c + 1 < NCH) {
            if (c + 2 < NCH) cpa_wait<1>(); else cpa_wait<0>();
            convert(c + 1);
        }

        uint32_t stA = sb + (uint32_t)(c % 3) * A_TILE_B;
        uint32_t stB = sb + DN_HBASE + (uint32_t)(c % 2) * B_TILE_B;

#pragma unroll
        for (int ks = 0; ks < 2; ks++) {
            int kb = ks * 16;
            uint32_t a[2][4];
#pragma unroll
            for (int mf = 0; mf < 2; mf++)
                ldm_x4(a[mf], stA + (uint32_t)(((wm + mf * 16 + a_row) * TS + kb + a_koff) * 2));

            int bk = kb + b_krow;
#pragma unroll
            for (int pf = 0; pf < 2; pf++) {
                int bn = wn + pf * 16 + b_noff;
                uint32_t b[4];
                ldm_x4_t(b, stB + (uint32_t)((bk * BS + bn) * 2));
#pragma unroll
                for (int sub = 0; sub < 2; sub++) {
                    int nf = pf * 2 + sub;
#pragma unroll
                    for (int mf = 0; mf < 2; mf++)
                        mma16(acc[mf][nf], a[mf], b + sub * 2);
                }
            }
        }
        __syncthreads();
    }

#pragma unroll
    for (int mf = 0; mf < 2; mf++) {
#pragma unroll
        for (int nf = 0; nf < 4; nf++) {
            int row0 = m0 + wm + mf * 16 + gr;
            int col  = n0 + wn + nf * 8 + qc;
            if (row0 < end)
                *(float2*)(g_y + (size_t)row0 * N + col) =
                    make_float2(acc[mf][nf][0], acc[mf][nf][1]);
            int row1 = row0 + 8;
            if (row1 < end)
                *(float2*)(g_y + (size_t)row1 * N + col) =
                    make_float2(acc[mf][nf][2], acc[mf][nf][3]);
        }
    }
}

// ---------------------------------------------------------------------------
// Combine: out[t] = w0 * y[p0] + w1 * y[p1]
// ---------------------------------------------------------------------------
__global__ void combine_kernel(float* __restrict__ out) {
    int t = blockIdx.x;
    int p0 = g_pos[2 * t], p1 = g_pos[2 * t + 1];
    float w0 = g_topW[2 * t], w1 = g_topW[2 * t + 1];
    const float4* y0 = (const float4*)(g_y + (size_t)p0 * H_DIM);
    const float4* y1 = (const float4*)(g_y + (size_t)p1 * H_DIM);
    float4* o = (float4*)(out + (size_t)t * H_DIM);
    float4 a = y0[threadIdx.x], b = y1[threadIdx.x];
    float4 v;
    v.x = w0 * a.x + w1 * b.x;
    v.y = w0 * a.y + w1 * b.y;
    v.z = w0 * a.z + w1 * b.z;
    v.w = w0 * a.w + w1 * b.w;
    o[threadIdx.x] = v;
}

// ---------------------------------------------------------------------------
extern "C" void kernel_launch(void* const* d_in, const int* in_sizes, int n_in,
                              void* d_out, int out_size) {
    const float* x   = (const float*)d_in[0];
    const float* wg  = (const float*)d_in[1];
    const float* wgp = (const float*)d_in[2];
    const float* wup = (const float*)d_in[3];
    const float* wdp = (const float*)d_in[4];
    float* out = (float*)d_out;

    int T = in_sizes[0] / H_DIM;   // 4096

    cudaFuncSetAttribute(gateup_kernel,
                         cudaFuncAttributeMaxDynamicSharedMemorySize, GU_SMEM);
    cudaFuncSetAttribute(down_kernel,
                         cudaFuncAttributeMaxDynamicSharedMemorySize, DN_SMEM);

    zero_kernel<<<1, 32>>>();
    router_kernel<<<(T + 7) / 8, 256>>>(x, wg, T);
    offsets_kernel<<<1, 1>>>();
    scatter_kernel<<<(2 * T + 255) / 256, 256>>>(T);
    gather_kernel<<<2 * T, 256>>>(x);

    dim3 g1(F_DIM / BN, (T + BM - 1) / BM, N_EXP);
    gateup_kernel<<<g1, NT, GU_SMEM>>>(wgp, wup);

    dim3 g2(H_DIM / BN, (T + BM - 1) / BM, N_EXP);
    down_kernel<<<g2, NT, DN_SMEM>>>(wdp);

    combine_kernel<<<T, 256>>>(out);
}

// round 15
// speedup vs baseline: 1.2294x; 1.2294x over previous
#include <cuda_runtime.h>
#include <cuda_fp16.h>
#include <cstdint>
#include <math.h>

#define H_DIM 1024
#define F_DIM 4096
#define N_EXP 8
#define MAX_T 4096
#define MAX_A (MAX_T * 2)

#define BM 128
#define BN 128
#define BK 32
#define TS 40                     // A smem stride (halves): 80 B, conflict-free
#define BS 136                    // B smem stride (halves): 272 B, conflict-free
#define A_TILE_B (BM * TS * 2)    // 10240 B
#define B_TILE_B (BK * BS * 2)    // 8704 B
#define A3 (3 * A_TILE_B)         // 30720: 3-deep A ring
#define GU_SMEM (A3 + 4 * B_TILE_B)   // + 2 slots x (gate+up) = 65536
#define DN_SMEM (A3 + 2 * B_TILE_B)   // + 2 slots x 1 matrix  = 48128

// ---------------------------------------------------------------------------
// Scratch (__device__ globals; referenced ONLY inside device code)
// ---------------------------------------------------------------------------
__device__ __half g_x16[(size_t)MAX_A * H_DIM];   // gathered x rows, fp16
__device__ __half g_h16[(size_t)MAX_A * F_DIM];   // silu(g)*u, fp16
__device__ float  g_y[(size_t)MAX_A * H_DIM];     // down output, fp32
__device__ int    g_counts[N_EXP];
__device__ int    g_offsets[N_EXP + 1];
__device__ int    g_cursor[N_EXP];
__device__ int    g_tok[MAX_A];
__device__ int    g_pos[MAX_A];
__device__ int    g_topE[MAX_A];
__device__ float  g_topW[MAX_A];

// ---------------------------------------------------------------------------
// helpers
// ---------------------------------------------------------------------------
__device__ __forceinline__ uint32_t smem_u32(const void* p) {
    uint32_t a;
    asm("{ .reg .u64 t; cvta.to.shared.u64 t, %1; cvt.u32.u64 %0, t; }" : "=r"(a) : "l"(p));
    return a;
}
__device__ __forceinline__ void cpa16(uint32_t s, const void* g) {
    asm volatile("cp.async.cg.shared.global [%0], [%1], 16;" :: "r"(s), "l"(g));
}
__device__ __forceinline__ void cpa_commit() { asm volatile("cp.async.commit_group;" ::: "memory"); }
template <int N> __device__ __forceinline__ void cpa_wait() {
    asm volatile("cp.async.wait_group %0;" :: "n"(N) : "memory");
}
__device__ __forceinline__ void mma16(float* c, const uint32_t* a, const uint32_t* b) {
    asm volatile(
        "mma.sync.aligned.m16n8k16.row.col.f32.f16.f16.f32 "
        "{%0,%1,%2,%3}, {%4,%5,%6,%7}, {%8,%9}, {%0,%1,%2,%3};"
        : "+f"(c[0]), "+f"(c[1]), "+f"(c[2]), "+f"(c[3])
        : "r"(a[0]), "r"(a[1]), "r"(a[2]), "r"(a[3]), "r"(b[0]), "r"(b[1]));
}
__device__ __forceinline__ void ldm_x4(uint32_t* r, uint32_t a) {
    asm volatile("ldmatrix.sync.aligned.m8n8.x4.shared.b16 {%0,%1,%2,%3}, [%4];"
        : "=r"(r[0]), "=r"(r[1]), "=r"(r[2]), "=r"(r[3]) : "r"(a));
}
__device__ __forceinline__ void ldm_x4_t(uint32_t* r, uint32_t a) {
    asm volatile("ldmatrix.sync.aligned.m8n8.x4.trans.shared.b16 {%0,%1,%2,%3}, [%4];"
        : "=r"(r[0]), "=r"(r[1]), "=r"(r[2]), "=r"(r[3]) : "r"(a));
}
// convert 8 fp32 (two float4) -> 8 fp16, single 16B smem store
__device__ __forceinline__ void sts8x(char* dst, float4 a, float4 b) {
    __half2 h0 = __floats2half2_rn(a.x, a.y);
    __half2 h1 = __floats2half2_rn(a.z, a.w);
    __half2 h2 = __floats2half2_rn(b.x, b.y);
    __half2 h3 = __floats2half2_rn(b.z, b.w);
    uint4 u = make_uint4(*(uint32_t*)&h0, *(uint32_t*)&h1,
                         *(uint32_t*)&h2, *(uint32_t*)&h3);
    *(uint4*)dst = u;
}

// ---------------------------------------------------------------------------
// Routing
// ---------------------------------------------------------------------------
__global__ void zero_kernel() {
    if (threadIdx.x < N_EXP) g_counts[threadIdx.x] = 0;
}

__global__ void router_kernel(const float* __restrict__ x,
                              const float* __restrict__ wg, int T) {
    int warp = (blockIdx.x * blockDim.x + threadIdx.x) >> 5;
    int lane = threadIdx.x & 31;
    if (warp >= T) return;
    const float* xr = x + (size_t)warp * H_DIM;

    float acc[N_EXP];
#pragma unroll
    for (int e = 0; e < N_EXP; e++) acc[e] = 0.0f;
    for (int k = lane; k < H_DIM; k += 32) {
        float xv = xr[k];
        const float* w = wg + (size_t)k * N_EXP;
#pragma unroll
        for (int e = 0; e < N_EXP; e++) acc[e] += xv * w[e];
    }
#pragma unroll
    for (int e = 0; e < N_EXP; e++)
#pragma unroll
        for (int o = 16; o > 0; o >>= 1)
            acc[e] += __shfl_xor_sync(0xFFFFFFFFu, acc[e], o);

    if (lane == 0) {
        float mx = acc[0];
#pragma unroll
        for (int e = 1; e < N_EXP; e++) mx = fmaxf(mx, acc[e]);
        float p[N_EXP], s = 0.0f;
#pragma unroll
        for (int e = 0; e < N_EXP; e++) { p[e] = __expf(acc[e] - mx); s += p[e]; }
        float inv = 1.0f / s;
        int e0 = 0;
#pragma unroll
        for (int e = 1; e < N_EXP; e++) if (p[e] > p[e0]) e0 = e;
        int e1 = (e0 == 0) ? 1 : 0;
#pragma unroll
        for (int e = 0; e < N_EXP; e++) if (e != e0 && p[e] > p[e1]) e1 = e;
        g_topE[warp * 2 + 0] = e0; g_topW[warp * 2 + 0] = p[e0] * inv;
        g_topE[warp * 2 + 1] = e1; g_topW[warp * 2 + 1] = p[e1] * inv;
        atomicAdd(&g_counts[e0], 1);
        atomicAdd(&g_counts[e1], 1);
    }
}

__global__ void offsets_kernel() {
    int s = 0;
    g_offsets[0] = 0;
#pragma unroll
    for (int e = 0; e < N_EXP; e++) {
        g_cursor[e] = s;
        s += g_counts[e];
        g_offsets[e + 1] = s;
    }
}

__global__ void scatter_kernel(int T) {
    int i = blockIdx.x * blockDim.x + threadIdx.x;
    if (i >= 2 * T) return;
    int e = g_topE[i];
    int pos = atomicAdd(&g_cursor[e], 1);
    g_tok[pos] = i >> 1;
    g_pos[i] = pos;
}

// Gather x rows into contiguous fp16 buffer.
__global__ void gather_kernel(const float* __restrict__ x) {
    int a = blockIdx.x;
    int tok = g_tok[a];
    const float4* src = (const float4*)(x + (size_t)tok * H_DIM);
    float4 v = src[threadIdx.x];
    __half2* dst = (__half2*)(g_x16 + (size_t)a * H_DIM) + threadIdx.x * 2;
    dst[0] = __floats2half2_rn(v.x, v.y);
    dst[1] = __floats2half2_rn(v.z, v.w);
}

// ---------------------------------------------------------------------------
// Fused gate+up GEMM. B read as fp32 from GMEM (LDG), converted in registers
// to the fp16 mma tile. No separate weight-convert pass.
// ---------------------------------------------------------------------------
__global__ __launch_bounds__(256)
void gateup_kernel(const float* __restrict__ Wg, const float* __restrict__ Wu) {
    constexpr int K = H_DIM, N = F_DIM, NCH = K / BK;

    int e = blockIdx.z;
    int beg = g_offsets[e], end = g_offsets[e + 1];
    int m0 = beg + (int)blockIdx.y * BM;
    if (m0 >= end) return;
    int n0 = blockIdx.x * BN;

    const float* Bg = Wg + (size_t)e * K * N + n0;
    const float* Bu = Wu + (size_t)e * K * N + n0;

    extern __shared__ char smem[];
    uint32_t sb = smem_u32(smem);

    int tid = threadIdx.x;
    int wid = tid >> 5, lane = tid & 31;
    int wm = (wid & 3) * 32;      // 4 warps along M
    int wn = (wid >> 2) * 64;     // 2 warps along N
    int gr = lane >> 2, qc = (lane & 3) * 2;

    int a_row = (lane & 15), a_koff = (lane >> 4) << 3;
    int b_krow = (lane & 7) + (((lane >> 3) & 1) << 3);
    int b_noff = (lane >> 4) << 3;

    // B load mapping: 32 k-rows x 8 threads; each thread covers cols
    // [8q,8q+7] and [8q+64,8q+71] of its k-row (4 float4 per matrix).
    int bkr = tid >> 3, bq = tid & 7;

    auto load_A = [&](int c) {
        uint32_t base = sb + (uint32_t)(c % 3) * A_TILE_B;
        int k0 = c * BK;
#pragma unroll
        for (int j = 0; j < 2; j++) {
            int idx = tid + j * 256;
            int row = idx >> 2, q = idx & 3;
            int r = m0 + row; if (r >= end) r = end - 1;
            cpa16(base + (uint32_t)(row * (TS * 2) + q * 16),
                  g_x16 + (size_t)r * K + k0 + q * 8);
        }
        cpa_commit();
    };

    float4 rg[4], ru[4];
    auto ldgB = [&](int c) {
        int k0 = c * BK;
        const float4* pg = (const float4*)(Bg + (size_t)(k0 + bkr) * N + bq * 8);
        const float4* pu = (const float4*)(Bu + (size_t)(k0 + bkr) * N + bq * 8);
        rg[0] = pg[0]; rg[1] = pg[1]; rg[2] = pg[16]; rg[3] = pg[17];
        ru[0] = pu[0]; ru[1] = pu[1]; ru[2] = pu[16]; ru[3] = pu[17];
    };
    auto cvtB = [&](int c) {
        char* hB = smem + A3 + (size_t)(c & 1) * (2 * B_TILE_B);
        int off = bkr * (BS * 2) + bq * 16;
        sts8x(hB + off,                    rg[0], rg[1]);
        sts8x(hB + off + 128,              rg[2], rg[3]);
        sts8x(hB + B_TILE_B + off,         ru[0], ru[1]);
        sts8x(hB + B_TILE_B + off + 128,   ru[2], ru[3]);
    };

    float accg[2][8][4], accu[2][8][4];
#pragma unroll
    for (int mf = 0; mf < 2; mf++)
#pragma unroll
        for (int nf = 0; nf < 8; nf++)
#pragma unroll
            for (int i = 0; i < 4; i++) { accg[mf][nf][i] = 0.0f; accu[mf][nf][i] = 0.0f; }

    load_A(0);
    load_A(1);
    ldgB(0);
    cvtB(0);          // stalls once on LDG(0); fills fp16 slot 0
    ldgB(1);          // in flight across chunk 0 compute
    cpa_wait<1>();    // A(0) resident
    __syncthreads();

    for (int c = 0; c < NCH; c++) {
        uint32_t stA  = sb + (uint32_t)(c % 3) * A_TILE_B;
        uint32_t stBg = sb + A3 + (uint32_t)(c & 1) * (2 * B_TILE_B);
        uint32_t stBu = stBg + B_TILE_B;

#pragma unroll
        for (int ks = 0; ks < 2; ks++) {
            int kb = ks * 16;
            uint32_t a[2][4];
#pragma unroll
            for (int mf = 0; mf < 2; mf++)
                ldm_x4(a[mf], stA + (uint32_t)(((wm + mf * 16 + a_row) * TS + kb + a_koff) * 2));

            int bk = kb + b_krow;
#pragma unroll
            for (int pf = 0; pf < 4; pf++) {
                int bn = wn + pf * 16 + b_noff;
                uint32_t bg[4], bu[4];
                ldm_x4_t(bg, stBg + (uint32_t)((bk * BS + bn) * 2));
                ldm_x4_t(bu, stBu + (uint32_t)((bk * BS + bn) * 2));
#pragma unroll
                for (int sub = 0; sub < 2; sub++) {
                    int nf = pf * 2 + sub;
#pragma unroll
                    for (int mf = 0; mf < 2; mf++) {
                        mma16(accg[mf][nf], a[mf], bg + sub * 2);
                        mma16(accu[mf][nf], a[mf], bu + sub * 2);
                    }
                }
            }
        }

        if (c + 1 < NCH) {
            cvtB(c + 1);                 // regs -> fp16 slot (c+1)&1
            if (c + 2 < NCH) ldgB(c + 2);// refill regs; full chunk to land
        }
        if (c + 2 < NCH) { load_A(c + 2); cpa_wait<1>(); }
        else if (c + 1 < NCH) { cpa_wait<0>(); }
        __syncthreads();
    }

    // epilogue: h = silu(g) * u, fp16
#pragma unroll
    for (int mf = 0; mf < 2; mf++) {
#pragma unroll
        for (int nf = 0; nf < 8; nf++) {
            int row0 = m0 + wm + mf * 16 + gr;
            int col  = n0 + wn + nf * 8 + qc;
            if (row0 < end) {
                float gv0 = accg[mf][nf][0], gv1 = accg[mf][nf][1];
                float h0 = (gv0 / (1.0f + __expf(-gv0))) * accu[mf][nf][0];
                float h1 = (gv1 / (1.0f + __expf(-gv1))) * accu[mf][nf][1];
                *(__half2*)(g_h16 + (size_t)row0 * F_DIM + col) = __floats2half2_rn(h0, h1);
            }
            int row1 = row0 + 8;
            if (row1 < end) {
                float gv2 = accg[mf][nf][2], gv3 = accg[mf][nf][3];
                float h2 = (gv2 / (1.0f + __expf(-gv2))) * accu[mf][nf][2];
                float h3 = (gv3 / (1.0f + __expf(-gv3))) * accu[mf][nf][3];
                *(__half2*)(g_h16 + (size_t)row1 * F_DIM + col) = __floats2half2_rn(h2, h3);
            }
        }
    }
}

// ---------------------------------------------------------------------------
// Down GEMM: y = h @ Wd (K=4096, N=1024). B fp32 via LDG-convert path.
// ---------------------------------------------------------------------------
__global__ __launch_bounds__(256)
void down_kernel(const float* __restrict__ Wd) {
    constexpr int K = F_DIM, N = H_DIM, NCH = K / BK;

    int e = blockIdx.z;
    int beg = g_offsets[e], end = g_offsets[e + 1];
    int m0 = beg + (int)blockIdx.y * BM;
    if (m0 >= end) return;
    int n0 = blockIdx.x * BN;

    const float* Bm = Wd + (size_t)e * K * N + n0;

    extern __shared__ char smem[];
    uint32_t sb = smem_u32(smem);

    int tid = threadIdx.x;
    int wid = tid >> 5, lane = tid & 31;
    int wm = (wid & 3) * 32;
    int wn = (wid >> 2) * 64;
    int gr = lane >> 2, qc = (lane & 3) * 2;

    int a_row = (lane & 15), a_koff = (lane >> 4) << 3;
    int b_krow = (lane & 7) + (((lane >> 3) & 1) << 3);
    int b_noff = (lane >> 4) << 3;

    int bkr = tid >> 3, bq = tid & 7;

    auto load_A = [&](int c) {
        uint32_t base = sb + (uint32_t)(c % 3) * A_TILE_B;
        int k0 = c * BK;
#pragma unroll
        for (int j = 0; j < 2; j++) {
            int idx = tid + j * 256;
            int row = idx >> 2, q = idx & 3;
            int r = m0 + row; if (r >= end) r = end - 1;
            cpa16(base + (uint32_t)(row * (TS * 2) + q * 16),
                  g_h16 + (size_t)r * K + k0 + q * 8);
        }
        cpa_commit();
    };

    float4 rb[4];
    auto ldgB = [&](int c) {
        int k0 = c * BK;
        const float4* pb = (const float4*)(Bm + (size_t)(k0 + bkr) * N + bq * 8);
        rb[0] = pb[0]; rb[1] = pb[1]; rb[2] = pb[16]; rb[3] = pb[17];
    };
    auto cvtB = [&](int c) {
        char* hB = smem + A3 + (size_t)(c & 1) * B_TILE_B;
        int off = bkr * (BS * 2) + bq * 16;
        sts8x(hB + off,       rb[0], rb[1]);
        sts8x(hB + off + 128, rb[2], rb[3]);
    };

    float acc[2][8][4];
#pragma unroll
    for (int mf = 0; mf < 2; mf++)
#pragma unroll
        for (int nf = 0; nf < 8; nf++)
#pragma unroll
            for (int i = 0; i < 4; i++) acc[mf][nf][i] = 0.0f;

    load_A(0);
    load_A(1);
    ldgB(0);
    cvtB(0);
    ldgB(1);
    cpa_wait<1>();
    __syncthreads();

    for (int c = 0; c < NCH; c++) {
        uint32_t stA = sb + (uint32_t)(c % 3) * A_TILE_B;
        uint32_t stB = sb + A3 + (uint32_t)(c & 1) * B_TILE_B;

#pragma unroll
        for (int ks = 0; ks < 2; ks++) {
            int kb = ks * 16;
            uint32_t a[2][4];
#pragma unroll
            for (int mf = 0; mf < 2; mf++)
                ldm_x4(a[mf], stA + (uint32_t)(((wm + mf * 16 + a_row) * TS + kb + a_koff) * 2));

            int bk = kb + b_krow;
#pragma unroll
            for (int pf = 0; pf < 4; pf++) {
                int bn = wn + pf * 16 + b_noff;
                uint32_t b[4];
                ldm_x4_t(b, stB + (uint32_t)((bk * BS + bn) * 2));
#pragma unroll
                for (int sub = 0; sub < 2; sub++) {
                    int nf = pf * 2 + sub;
#pragma unroll
                    for (int mf = 0; mf < 2; mf++)
                        mma16(acc[mf][nf], a[mf], b + sub * 2);
                }
            }
        }

        if (c + 1 < NCH) {
            cvtB(c + 1);
            if (c + 2 < NCH) ldgB(c + 2);
        }
        if (c + 2 < NCH) { load_A(c + 2); cpa_wait<1>(); }
        else if (c + 1 < NCH) { cpa_wait<0>(); }
        __syncthreads();
    }

#pragma unroll
    for (int mf = 0; mf < 2; mf++) {
#pragma unroll
        for (int nf = 0; nf < 8; nf++) {
            int row0 = m0 + wm + mf * 16 + gr;
            int col  = n0 + wn + nf * 8 + qc;
            if (row0 < end)
                *(float2*)(g_y + (size_t)row0 * N + col) =
                    make_float2(acc[mf][nf][0], acc[mf][nf][1]);
            int row1 = row0 + 8;
            if (row1 < end)
                *(float2*)(g_y + (size_t)row1 * N + col) =
                    make_float2(acc[mf][nf][2], acc[mf][nf][3]);
        }
    }
}

// ---------------------------------------------------------------------------
// Combine: out[t] = w0 * y[p0] + w1 * y[p1]
// ---------------------------------------------------------------------------
__global__ void combine_kernel(float* __restrict__ out) {
    int t = blockIdx.x;
    int p0 = g_pos[2 * t], p1 = g_pos[2 * t + 1];
    float w0 = g_topW[2 * t], w1 = g_topW[2 * t + 1];
    const float4* y0 = (const float4*)(g_y + (size_t)p0 * H_DIM);
    const float4* y1 = (const float4*)(g_y + (size_t)p1 * H_DIM);
    float4* o = (float4*)(out + (size_t)t * H_DIM);
    float4 a = y0[threadIdx.x], b = y1[threadIdx.x];
    float4 v;
    v.x = w0 * a.x + w1 * b.x;
    v.y = w0 * a.y + w1 * b.y;
    v.z = w0 * a.z + w1 * b.z;
    v.w = w0 * a.w + w1 * b.w;
    o[threadIdx.x] = v;
}

// ---------------------------------------------------------------------------
extern "C" void kernel_launch(void* const* d_in, const int* in_sizes, int n_in,
                              void* d_out, int out_size) {
    const float* x   = (const float*)d_in[0];
    const float* wg  = (const float*)d_in[1];
    const float* wgp = (const float*)d_in[2];
    const float* wup = (const float*)d_in[3];
    const float* wdp = (const float*)d_in[4];
    float* out = (float*)d_out;

    int T = in_sizes[0] / H_DIM;   // 4096

    cudaFuncSetAttribute(gateup_kernel,
                         cudaFuncAttributeMaxDynamicSharedMemorySize, GU_SMEM);
    cudaFuncSetAttribute(down_kernel,
                         cudaFuncAttributeMaxDynamicSharedMemorySize, DN_SMEM);

    zero_kernel<<<1, 32>>>();
    router_kernel<<<(T + 7) / 8, 256>>>(x, wg, T);
    offsets_kernel<<<1, 1>>>();
    scatter_kernel<<<(2 * T + 255) / 256, 256>>>(T);
    gather_kernel<<<2 * T, 256>>>(x);

    dim3 g1(F_DIM / BN, (T + BM - 1) / BM, N_EXP);
    gateup_kernel<<<g1, 256, GU_SMEM>>>(wgp, wup);

    dim3 g2(H_DIM / BN, (T + BM - 1) / BM, N_EXP);
    down_kernel<<<g2, 256, DN_SMEM>>>(wdp);

    combine_kernel<<<T, 256>>>(out);
}